// round 4
// baseline (speedup 1.0000x reference)
#include <cuda_runtime.h>

// ---------------------------------------------------------------------------
// AttentiveStateMLP fused kernel.
// B=131072 rows, each: 5 encoders -> 5 tokens(64) -> qkv -> 4-head attn(S=5)
// -> out proj -> residual+LN -> mean pool -> 128-dim relu head.
//
// Optimization: qkv[s] = Wqkv @ (P_s @ f_s + pb_s) + bqkv
//             = (Wqkv @ P_s) @ f_s + (Wqkv @ pb_s + bqkv)
// The fused matrices (192 x 144 total) are precomputed each launch by a tiny
// prep kernel into __device__ globals (graph-capturable, no allocs).
// Main kernel: one warp per row, 8 rows / 256-thread block.
// ---------------------------------------------------------------------------

#define BATCH 131072
#define WARPS_PER_BLOCK 8
#define ROW_SMEM 1488   // floats per row: sx/pooled 64 | f 144 | qkv 960 | ctx 320

__device__ float g_WP[192 * 144];  // fused (Wqkv @ P_s), column blocks per segment
__device__ float g_qb[5 * 192];    // fused bias per token: Wqkv @ pb_s + bqkv

// segment column offsets within the 144-wide feature vector, and dims
// phys[0:64] obj[64:96] mine[96:112] prog[112:128] seq[128:144]

__global__ void prep_kernel(
    const float* __restrict__ Wqkv, const float* __restrict__ bqkv,
    const float* __restrict__ P_phys, const float* __restrict__ pb_phys,
    const float* __restrict__ P_obj,  const float* __restrict__ pb_obj,
    const float* __restrict__ P_mine, const float* __restrict__ pb_mine,
    const float* __restrict__ P_prog, const float* __restrict__ pb_prog,
    const float* __restrict__ P_seq,  const float* __restrict__ pb_seq)
{
    int idx = blockIdx.x * blockDim.x + threadIdx.x;
    if (idx < 192 * 144) {
        int j = idx / 144;
        int col = idx - j * 144;
        const float* P; int d, dim;
        if (col < 64)       { P = P_phys; d = col;       dim = 64; }
        else if (col < 96)  { P = P_obj;  d = col - 64;  dim = 32; }
        else if (col < 112) { P = P_mine; d = col - 96;  dim = 16; }
        else if (col < 128) { P = P_prog; d = col - 112; dim = 16; }
        else                { P = P_seq;  d = col - 128; dim = 16; }
        float acc = 0.f;
        #pragma unroll 8
        for (int c = 0; c < 64; c++) acc = fmaf(Wqkv[j * 64 + c], P[c * dim + d], acc);
        g_WP[idx] = acc;
    }
    if (idx < 5 * 192) {
        int s = idx / 192;
        int j = idx - s * 192;
        const float* pb = (s == 0) ? pb_phys : (s == 1) ? pb_obj :
                          (s == 2) ? pb_mine : (s == 3) ? pb_prog : pb_seq;
        float acc = bqkv[j];
        #pragma unroll 8
        for (int c = 0; c < 64; c++) acc = fmaf(Wqkv[j * 64 + c], pb[c], acc);
        g_qb[idx] = acc;
    }
}

__device__ __forceinline__ float dot4(float4 a, float4 b, float acc) {
    acc = fmaf(a.x, b.x, acc);
    acc = fmaf(a.y, b.y, acc);
    acc = fmaf(a.z, b.z, acc);
    acc = fmaf(a.w, b.w, acc);
    return acc;
}

template <int DIM>
__device__ __forceinline__ void token_pair(
    const float* __restrict__ P, const float* __restrict__ pb,
    const float* sfseg, int lane, float& t0, float& t1)
{
    float a0 = pb[lane], a1 = pb[lane + 32];
    const float4* p0 = reinterpret_cast<const float4*>(P + lane * DIM);
    const float4* p1 = reinterpret_cast<const float4*>(P + (lane + 32) * DIM);
    const float4* fv = reinterpret_cast<const float4*>(sfseg);
    #pragma unroll
    for (int k = 0; k < DIM / 4; k++) {
        float4 f = fv[k];
        a0 = dot4(p0[k], f, a0);
        a1 = dot4(p1[k], f, a1);
    }
    t0 = a0; t1 = a1;
}

__global__ __launch_bounds__(WARPS_PER_BLOCK * 32, 2)
void fused_kernel(
    const float* __restrict__ x,
    const float* __restrict__ W_phys, const float* __restrict__ b_phys,
    const float* __restrict__ W_obj,  const float* __restrict__ b_obj,
    const float* __restrict__ W_mine, const float* __restrict__ b_mine,
    const float* __restrict__ W_prog, const float* __restrict__ b_prog,
    const float* __restrict__ W_seq,  const float* __restrict__ b_seq,
    const float* __restrict__ P_phys, const float* __restrict__ pb_phys,
    const float* __restrict__ P_obj,  const float* __restrict__ pb_obj,
    const float* __restrict__ P_mine, const float* __restrict__ pb_mine,
    const float* __restrict__ P_prog, const float* __restrict__ pb_prog,
    const float* __restrict__ P_seq,  const float* __restrict__ pb_seq,
    const float* __restrict__ Wo, const float* __restrict__ bo,
    const float* __restrict__ gamma, const float* __restrict__ beta,
    const float* __restrict__ Wp, const float* __restrict__ bp,
    float* __restrict__ out)
{
    __shared__ float smem[WARPS_PER_BLOCK][ROW_SMEM];
    const int warp = threadIdx.x >> 5;
    const int lane = threadIdx.x & 31;
    const int row  = blockIdx.x * WARPS_PER_BLOCK + warp;

    float* S     = smem[warp];
    float* sx    = S;            // 64 floats: x (58 used); later reused for pooled
    float* sf    = S + 64;       // 144 floats: relu features
    float* sqkv  = S + 208;      // 960 floats: qkv per token (5 x 192)
    float* sctx  = S + 1168;     // 320 floats: attention context (5 x 64)

    // ---- load x row into smem ----
    const float* xr = x + (size_t)row * 58;
    sx[lane] = xr[lane];
    if (lane < 26) sx[lane + 32] = xr[lane + 32];
    __syncwarp();

    // ---- feature encoders (relu MLPs) ----
    {   // phys: 64 outputs, dot over x[0:29]
        float a0 = b_phys[lane], a1 = b_phys[lane + 32];
        const float* w0 = W_phys + lane * 29;
        const float* w1 = W_phys + (lane + 32) * 29;
        #pragma unroll
        for (int k = 0; k < 29; k++) {
            float xv = sx[k];
            a0 = fmaf(w0[k], xv, a0);
            a1 = fmaf(w1[k], xv, a1);
        }
        sf[lane] = fmaxf(a0, 0.f);
        sf[lane + 32] = fmaxf(a1, 0.f);
    }
    {   // obj: 32 outputs, dot over x[29:44]
        float a = b_obj[lane];
        const float* w = W_obj + lane * 15;
        #pragma unroll
        for (int k = 0; k < 15; k++) a = fmaf(w[k], sx[29 + k], a);
        sf[64 + lane] = fmaxf(a, 0.f);
    }
    if (lane < 16) {
        // mine: 16 outputs, dot x[44:52]
        float a = b_mine[lane];
        const float* w = W_mine + lane * 8;
        #pragma unroll
        for (int k = 0; k < 8; k++) a = fmaf(w[k], sx[44 + k], a);
        sf[96 + lane] = fmaxf(a, 0.f);
        // prog: 16 outputs, dot x[52:55]
        float b = b_prog[lane];
        const float* wq = W_prog + lane * 3;
        #pragma unroll
        for (int k = 0; k < 3; k++) b = fmaf(wq[k], sx[52 + k], b);
        sf[112 + lane] = fmaxf(b, 0.f);
        // seq: 16 outputs, dot x[55:58]
        float c = b_seq[lane];
        const float* ws = W_seq + lane * 3;
        #pragma unroll
        for (int k = 0; k < 3; k++) c = fmaf(ws[k], sx[55 + k], c);
        sf[128 + lane] = fmaxf(c, 0.f);
    }
    __syncwarp();

    // ---- tokens (needed for residual): token[s][c], c = lane, lane+32 ----
    float tok0[5], tok1[5];
    token_pair<64>(P_phys, pb_phys, sf +   0, lane, tok0[0], tok1[0]);
    token_pair<32>(P_obj,  pb_obj,  sf +  64, lane, tok0[1], tok1[1]);
    token_pair<16>(P_mine, pb_mine, sf +  96, lane, tok0[2], tok1[2]);
    token_pair<16>(P_prog, pb_prog, sf + 112, lane, tok0[3], tok1[3]);
    token_pair<16>(P_seq,  pb_seq,  sf + 128, lane, tok0[4], tok1[4]);

    // ---- fused qkv: qkv[s][j] = g_qb[s][j] + WP[j, seg_s] . f_seg_s ----
    {
        const int SEG_OFF[5] = {0, 64, 96, 112, 128};
        const int SEG_DIM[5] = {64, 32, 16, 16, 16};
        #pragma unroll
        for (int s = 0; s < 5; s++) {
            const int off = SEG_OFF[s];
            const int dim = SEG_DIM[s];
            const float4* fv = reinterpret_cast<const float4*>(sf + off);
            float acc[6];
            #pragma unroll
            for (int m = 0; m < 6; m++) acc[m] = g_qb[s * 192 + lane + 32 * m];
            #pragma unroll
            for (int k = 0; k < dim / 4; k++) {
                float4 f = fv[k];
                #pragma unroll
                for (int m = 0; m < 6; m++) {
                    const float4 w = *reinterpret_cast<const float4*>(
                        g_WP + (lane + 32 * m) * 144 + off + 4 * k);
                    acc[m] = dot4(w, f, acc[m]);
                }
            }
            #pragma unroll
            for (int m = 0; m < 6; m++) sqkv[s * 192 + lane + 32 * m] = acc[m];
        }
    }
    __syncwarp();

    // ---- attention: lanes 0..19, unit (head h, query token i) ----
    if (lane < 20) {
        const int h = lane / 5;
        const int i = lane - h * 5;
        const float* q = sqkv + i * 192 + h * 16;
        float sc[5];
        #pragma unroll
        for (int j = 0; j < 5; j++) {
            const float* kk = sqkv + j * 192 + 64 + h * 16;
            float d = 0.f;
            #pragma unroll
            for (int t = 0; t < 16; t++) d = fmaf(q[t], kk[t], d);
            sc[j] = d * 0.25f;   // / sqrt(HD=16)
        }
        float mx = sc[0];
        #pragma unroll
        for (int j = 1; j < 5; j++) mx = fmaxf(mx, sc[j]);
        float sum = 0.f;
        #pragma unroll
        for (int j = 0; j < 5; j++) { sc[j] = __expf(sc[j] - mx); sum += sc[j]; }
        const float inv = 1.f / sum;
        #pragma unroll
        for (int t = 0; t < 16; t++) {
            float c = 0.f;
            #pragma unroll
            for (int j = 0; j < 5; j++)
                c = fmaf(sc[j], sqkv[j * 192 + 128 + h * 16 + t], c);
            sctx[i * 64 + h * 16 + t] = c * inv;
        }
    }
    __syncwarp();

    // ---- out proj + residual + LayerNorm + pool ----
    float p0 = 0.f, p1 = 0.f;
    const float g0 = gamma[lane], g1 = gamma[lane + 32];
    const float be0 = beta[lane], be1 = beta[lane + 32];
    const float bo0 = bo[lane],   bo1 = bo[lane + 32];
    const float4* w0 = reinterpret_cast<const float4*>(Wo + lane * 64);
    const float4* w1 = reinterpret_cast<const float4*>(Wo + (lane + 32) * 64);
    #pragma unroll
    for (int s = 0; s < 5; s++) {
        float a0 = bo0, a1 = bo1;
        const float4* cv = reinterpret_cast<const float4*>(sctx + s * 64);
        #pragma unroll
        for (int k = 0; k < 16; k++) {
            float4 c = cv[k];
            a0 = dot4(w0[k], c, a0);
            a1 = dot4(w1[k], c, a1);
        }
        float h0 = tok0[s] + a0;
        float h1 = tok1[s] + a1;
        // mean over 64 = warp-sum of (h0 + h1) / 64
        float sum = h0 + h1;
        #pragma unroll
        for (int o = 16; o > 0; o >>= 1) sum += __shfl_xor_sync(0xffffffff, sum, o);
        const float mu = sum * (1.f / 64.f);
        const float d0 = h0 - mu, d1 = h1 - mu;
        float v = d0 * d0 + d1 * d1;
        #pragma unroll
        for (int o = 16; o > 0; o >>= 1) v += __shfl_xor_sync(0xffffffff, v, o);
        const float invstd = rsqrtf(v * (1.f / 64.f) + 1e-5f);
        p0 = fmaf(d0 * invstd, g0, p0 + be0);
        p1 = fmaf(d1 * invstd, g1, p1 + be1);
    }
    p0 *= 0.2f;
    p1 *= 0.2f;
    __syncwarp();
    sx[lane] = p0;           // reuse x region for pooled vector
    sx[lane + 32] = p1;
    __syncwarp();

    // ---- head: out[o] = relu(Wp[o] . pooled + bp[o]), o = lane + 32m ----
    const float4* pv = reinterpret_cast<const float4*>(sx);
    float* orow = out + (size_t)row * 128;
    #pragma unroll
    for (int m = 0; m < 4; m++) {
        const int o = lane + 32 * m;
        float a = bp[o];
        const float4* w = reinterpret_cast<const float4*>(Wp + o * 64);
        #pragma unroll
        for (int k = 0; k < 16; k++) a = dot4(w[k], pv[k], a);
        orow[o] = fmaxf(a, 0.f);
    }
}

extern "C" void kernel_launch(void* const* d_in, const int* in_sizes, int n_in,
                              void* d_out, int out_size)
{
    const float* x       = (const float*)d_in[0];
    const float* W_phys  = (const float*)d_in[1];
    const float* b_phys  = (const float*)d_in[2];
    const float* W_obj   = (const float*)d_in[3];
    const float* b_obj   = (const float*)d_in[4];
    const float* W_mine  = (const float*)d_in[5];
    const float* b_mine  = (const float*)d_in[6];
    const float* W_prog  = (const float*)d_in[7];
    const float* b_prog  = (const float*)d_in[8];
    const float* W_seq   = (const float*)d_in[9];
    const float* b_seq   = (const float*)d_in[10];
    const float* P_phys  = (const float*)d_in[11];
    const float* pb_phys = (const float*)d_in[12];
    const float* P_obj   = (const float*)d_in[13];
    const float* pb_obj  = (const float*)d_in[14];
    const float* P_mine  = (const float*)d_in[15];
    const float* pb_mine = (const float*)d_in[16];
    const float* P_prog  = (const float*)d_in[17];
    const float* pb_prog = (const float*)d_in[18];
    const float* P_seq   = (const float*)d_in[19];
    const float* pb_seq  = (const float*)d_in[20];
    const float* Wqkv    = (const float*)d_in[21];
    const float* bqkv    = (const float*)d_in[22];
    const float* Wo      = (const float*)d_in[23];
    const float* bo      = (const float*)d_in[24];
    const float* gamma   = (const float*)d_in[25];
    const float* beta    = (const float*)d_in[26];
    const float* Wp      = (const float*)d_in[27];
    const float* bp      = (const float*)d_in[28];
    float* out = (float*)d_out;

    prep_kernel<<<108, 256>>>(Wqkv, bqkv, P_phys, pb_phys, P_obj, pb_obj,
                              P_mine, pb_mine, P_prog, pb_prog, P_seq, pb_seq);

    fused_kernel<<<BATCH / WARPS_PER_BLOCK, WARPS_PER_BLOCK * 32>>>(
        x,
        W_phys, b_phys, W_obj, b_obj, W_mine, b_mine,
        W_prog, b_prog, W_seq, b_seq,
        P_phys, pb_phys, P_obj, pb_obj, P_mine, pb_mine,
        P_prog, pb_prog, P_seq, pb_seq,
        Wo, bo, gamma, beta, Wp, bp,
        out);
}